// round 8
// baseline (speedup 1.0000x reference)
#include <cuda_runtime.h>
#include <cuda_fp16.h>
#include <mma.h>
#include <cstdint>

using namespace nvcuda;
typedef unsigned int u32;

#define TILE 128
#define LDH 264            // hs fp16 stride (528B)
#define LDB 264            // B fp16 stride (528B)
#define LDFS 260           // fs fp32 stride

// ---------------- smem layout (floats) ----------------
// Bres: 256 x 264 fp16 = 33792 floats   [0, 33792)
// hs  : 128 x 264 fp16 = 16896 floats   [33792, 50688)   (fs 64x260 fp32 overlays)
// lfws: 5120                            [50688, 55808)
// lfbs: 32                              [55808, 55840)
#define BRES_F 0
#define HS_F   33792
#define LFW_F  50688
#define LFB_F  55808
#define SMEM_FLOATS 55840            // 223,360 B (1 CTA/SM)

__device__ __half g_w2h[256 * 256];   // [K][N] fp16
__device__ float  g_lfwp[256 * 20];   // lfw padded to stride 20

__device__ __forceinline__ u32 smem_u32(const void* p) {
    return (u32)__cvta_generic_to_shared(p);
}
__device__ __forceinline__ void cp_async16(u32 s, const void* g) {
    asm volatile("cp.async.cg.shared.global [%0], [%1], 16;" :: "r"(s), "l"(g));
}
__device__ __forceinline__ void cp_commit() { asm volatile("cp.async.commit_group;"); }
template<int NN> __device__ __forceinline__ void cp_wait() {
    asm volatile("cp.async.wait_group %0;" :: "n"(NN) : "memory");
}

__global__ void w2_convert_kernel(const float* __restrict__ w2,
                                  const float* __restrict__ lfw) {
    const int k = blockIdx.x, n = threadIdx.x;
    g_w2h[k * 256 + n] = __float2half(w2[k * 256 + n]);
    if (k < 18)      g_lfwp[n * 20 + k] = lfw[n * 18 + k];
    else if (k < 20) g_lfwp[n * 20 + k] = 0.f;
}

// =================== Persistent fused kernel ===================
__global__ void __launch_bounds__(512, 1)
gauss_persist_kernel(const float* __restrict__ mu, const float* __restrict__ sc,
                     const float* __restrict__ rot, const float* __restrict__ Q,
                     const float* __restrict__ w1, const float* __restrict__ b1,
                     const float* __restrict__ gamma, const float* __restrict__ beta,
                     const float* __restrict__ b2, const float* __restrict__ lfb,
                     float* __restrict__ out, int N, int ntiles)
{
    extern __shared__ float sm[];
    const u32 smb = smem_u32(sm);
    const __half* Bres = (const __half*)(sm + BRES_F);
    __half* hs  = (__half*)(sm + HS_F);
    float* fs   = sm + HS_F;          // overlays hs post-GEMM (per half)
    float* lfws = sm + LFW_F;
    float* lfbs = sm + LFB_F;

    const int tid  = threadIdx.x;
    const int lane = tid & 31;
    const int wid  = tid >> 5;

    // ---- one-time: stage B (fp16, 135KB) + lfw into smem ----
    {
        #pragma unroll
        for (int i = 0; i < 16; ++i) {
            const int idx = tid + 512 * i;       // 0..8191
            const int r = idx >> 5, j = idx & 31;
            cp_async16(smb + BRES_F * 4 + r * 528 + j * 16, g_w2h + r * 256 + j * 8);
        }
        #pragma unroll
        for (int i = 0; i < 3; ++i) {
            const int c = tid + 512 * i;
            if (c < 1280) cp_async16(smb + (LFW_F + c * 4) * 4, g_lfwp + c * 4);
        }
    }
    cp_commit();
    if (tid < 18) lfbs[tid] = lfb[tid];
    const int myCol = tid & 255;
    const float b2v = __ldg(b2 + myCol);
    cp_wait<0>();
    __syncthreads();

    const int wm = wid & 3;          // m-group (32 rows)
    const int wn = wid >> 2;         // n-group (64 cols)

    // ---- persistent tile loop ----
    for (int tile = blockIdx.x; tile < ntiles; tile += gridDim.x) {
        const int rowBase = tile * TILE;

        // ---- phase 1: h = relu(LN(geo@w1+b1)) -> hs fp16 (16 warps x 8 rows) ----
        #pragma unroll 1
        for (int bb = 0; bb < 2; ++bb) {
            const int rl0 = wid * 8 + bb * 4;
            float g[4][10];
            #pragma unroll
            for (int r = 0; r < 4; ++r) {
                const int row = rowBase + rl0 + r;
                if (row < N) {
                    g[r][0]=__ldg(mu+row*3);  g[r][1]=__ldg(mu+row*3+1);  g[r][2]=__ldg(mu+row*3+2);
                    g[r][3]=__ldg(sc+row*3);  g[r][4]=__ldg(sc+row*3+1);  g[r][5]=__ldg(sc+row*3+2);
                    g[r][6]=__ldg(rot+row*4); g[r][7]=__ldg(rot+row*4+1); g[r][8]=__ldg(rot+row*4+2); g[r][9]=__ldg(rot+row*4+3);
                } else {
                    #pragma unroll
                    for (int i = 0; i < 10; ++i) g[r][i] = 0.f;
                }
            }
            float hv[4][8];
            #pragma unroll
            for (int jj = 0; jj < 8; ++jj) {
                const int d = lane + 32 * jj;
                float w[10];
                #pragma unroll
                for (int i = 0; i < 10; ++i) w[i] = __ldg(w1 + i * 256 + d);
                const float bv = __ldg(b1 + d);
                #pragma unroll
                for (int r = 0; r < 4; ++r) {
                    float a = bv;
                    #pragma unroll
                    for (int i = 0; i < 10; ++i) a = fmaf(g[r][i], w[i], a);
                    hv[r][jj] = a;
                }
            }
            float s[4] = {0.f, 0.f, 0.f, 0.f};
            #pragma unroll
            for (int r = 0; r < 4; ++r)
                #pragma unroll
                for (int jj = 0; jj < 8; ++jj) s[r] += hv[r][jj];
            #pragma unroll
            for (int o = 16; o; o >>= 1) {
                #pragma unroll
                for (int r = 0; r < 4; ++r) s[r] += __shfl_xor_sync(0xffffffffu, s[r], o);
            }
            float v[4] = {0.f, 0.f, 0.f, 0.f};
            float mean[4];
            #pragma unroll
            for (int r = 0; r < 4; ++r) {
                mean[r] = s[r] * (1.f/256.f);
                #pragma unroll
                for (int jj = 0; jj < 8; ++jj) { float t = hv[r][jj] - mean[r]; v[r] = fmaf(t, t, v[r]); }
            }
            #pragma unroll
            for (int o = 16; o; o >>= 1) {
                #pragma unroll
                for (int r = 0; r < 4; ++r) v[r] += __shfl_xor_sync(0xffffffffu, v[r], o);
            }
            #pragma unroll
            for (int r = 0; r < 4; ++r) {
                const float inv = rsqrtf(v[r] * (1.f/256.f) + 1e-5f);
                const bool valid = (rowBase + rl0 + r < N);
                #pragma unroll
                for (int jj = 0; jj < 8; ++jj) {
                    const int d = lane + 32 * jj;
                    float t = (hv[r][jj] - mean[r]) * inv * __ldg(gamma + d) + __ldg(beta + d);
                    t = fmaxf(t, 0.f);
                    if (!valid) t = 0.f;
                    hs[(rl0 + r) * LDH + d] = __float2half(t);
                }
            }
        }
        __syncthreads();

        // ---- phase 2: GEMM 128x256x256, no syncs, no loads from global ----
        wmma::fragment<wmma::accumulator, 16,16,16, float> acc[2][4];
        #pragma unroll
        for (int mi = 0; mi < 2; ++mi)
            #pragma unroll
            for (int ni = 0; ni < 4; ++ni) wmma::fill_fragment(acc[mi][ni], 0.f);

        #pragma unroll 1
        for (int t = 0; t < 16; ++t) {
            const int kk = t * 16;
            wmma::fragment<wmma::matrix_a, 16,16,16, __half, wmma::row_major> a[2];
            #pragma unroll
            for (int mi = 0; mi < 2; ++mi)
                wmma::load_matrix_sync(a[mi], hs + (wm*32 + mi*16) * LDH + kk, LDH);
            #pragma unroll
            for (int ni = 0; ni < 4; ++ni) {
                wmma::fragment<wmma::matrix_b, 16,16,16, __half, wmma::row_major> b;
                wmma::load_matrix_sync(b, Bres + kk * LDB + wn*64 + ni*16, LDB);
                wmma::mma_sync(acc[0][ni], a[0], b, acc[0][ni]);
                wmma::mma_sync(acc[1][ni], a[1], b, acc[1][ni]);
            }
        }
        __syncthreads();   // hs dead -> fs region

        // ---- epilogue + phase 4, two 64-row halves ----
        #pragma unroll 1
        for (int h = 0; h < 2; ++h) {
            // store this half's accumulators (warps wm in {2h, 2h+1})
            if ((wm >> 1) == h) {
                #pragma unroll
                for (int mi = 0; mi < 2; ++mi)
                    #pragma unroll
                    for (int ni = 0; ni < 4; ++ni)
                        wmma::store_matrix_sync(fs + ((wm & 1)*32 + mi*16) * LDFS + wn*64 + ni*16,
                                                acc[mi][ni], LDFS, wmma::mem_row_major);
            }
            __syncthreads();

            // features = E + b2 + Q -> out + fs
            {
                const int r2 = tid >> 8;     // 0 or 1
                #pragma unroll 1
                for (int rbb = 0; rbb < 4; ++rbb) {
                    float qv[8];
                    #pragma unroll
                    for (int j = 0; j < 8; ++j) {
                        const int rloc = r2 + (rbb*8 + j) * 2;
                        const int row = rowBase + 64*h + rloc;
                        qv[j] = (row < N) ? Q[(size_t)row * 256 + myCol] : 0.f;
                    }
                    #pragma unroll
                    for (int j = 0; j < 8; ++j) {
                        const int rloc = r2 + (rbb*8 + j) * 2;
                        const int row = rowBase + 64*h + rloc;
                        const float v = fs[rloc * LDFS + myCol] + b2v + qv[j];
                        if (row < N) out[(size_t)row * 256 + myCol] = v;
                        fs[rloc * LDFS + myCol] = v;
                    }
                }
            }
            __syncthreads();

            // phase 4: lf matmul + corners + refs (warp = 4 rows x 8 col-parts)
            {
                const int rl    = wid * 4 + (lane >> 3);     // 0..63 within half
                const int cpart = lane & 7;
                const int row   = rowBase + 64*h + rl;
                float s[18];
                #pragma unroll
                for (int j = 0; j < 18; ++j) s[j] = 0.f;
                const int cbase = cpart * 32;
                #pragma unroll 1
                for (int u = 0; u < 32; u += 4) {
                    float4 fv = *(const float4*)&fs[rl * LDFS + cbase + u];
                    const float fvals[4] = {fv.x, fv.y, fv.z, fv.w};
                    #pragma unroll
                    for (int p = 0; p < 4; ++p) {
                        const float f = fvals[p];
                        const int c = cbase + u + p;
                        const float4 l0 = *(const float4*)&lfws[c*20 + 0];
                        const float4 l1 = *(const float4*)&lfws[c*20 + 4];
                        const float4 l2 = *(const float4*)&lfws[c*20 + 8];
                        const float4 l3 = *(const float4*)&lfws[c*20 + 12];
                        const float2 l4 = *(const float2*)&lfws[c*20 + 16];
                        s[0]  = fmaf(f, l0.x, s[0]);  s[1]  = fmaf(f, l0.y, s[1]);
                        s[2]  = fmaf(f, l0.z, s[2]);  s[3]  = fmaf(f, l0.w, s[3]);
                        s[4]  = fmaf(f, l1.x, s[4]);  s[5]  = fmaf(f, l1.y, s[5]);
                        s[6]  = fmaf(f, l1.z, s[6]);  s[7]  = fmaf(f, l1.w, s[7]);
                        s[8]  = fmaf(f, l2.x, s[8]);  s[9]  = fmaf(f, l2.y, s[9]);
                        s[10] = fmaf(f, l2.z, s[10]); s[11] = fmaf(f, l2.w, s[11]);
                        s[12] = fmaf(f, l3.x, s[12]); s[13] = fmaf(f, l3.y, s[13]);
                        s[14] = fmaf(f, l3.z, s[14]); s[15] = fmaf(f, l3.w, s[15]);
                        s[16] = fmaf(f, l4.x, s[16]); s[17] = fmaf(f, l4.y, s[17]);
                    }
                }
                #pragma unroll
                for (int j = 0; j < 18; ++j) {
                    s[j] += __shfl_xor_sync(0xffffffffu, s[j], 1);
                    s[j] += __shfl_xor_sync(0xffffffffu, s[j], 2);
                    s[j] += __shfl_xor_sync(0xffffffffu, s[j], 4);
                }

                if (row < N) {
                    const float mx = __ldg(mu+row*3), my = __ldg(mu+row*3+1), mz = __ldg(mu+row*3+2);
                    const float sx = __ldg(sc+row*3)*0.5f, sy = __ldg(sc+row*3+1)*0.5f, sz = __ldg(sc+row*3+2)*0.5f;
                    float qw = __ldg(rot+row*4), qx = __ldg(rot+row*4+1), qy = __ldg(rot+row*4+2), qz = __ldg(rot+row*4+3);
                    const float nrm = fmaxf(sqrtf(qw*qw + qx*qx + qy*qy + qz*qz), 1e-8f);
                    const float inr = 1.f / nrm;
                    qw *= inr; qx *= inr; qy *= inr; qz *= inr;
                    const float r00 = 1.f - 2.f*(qy*qy + qz*qz), r01 = 2.f*(qx*qy - qz*qw), r02 = 2.f*(qx*qz + qy*qw);
                    const float r10 = 2.f*(qx*qy + qz*qw), r11 = 1.f - 2.f*(qx*qx + qz*qz), r12 = 2.f*(qy*qz - qx*qw);
                    const float r20 = 2.f*(qx*qz - qy*qw), r21 = 2.f*(qy*qz + qx*qw), r22 = 1.f - 2.f*(qx*qx + qy*qy);

                    const size_t OUT_CORN = (size_t)N * 256;
                    const size_t OUT_XY   = OUT_CORN + (size_t)N * 33;
                    const size_t OUT_XZ   = OUT_XY + (size_t)N * 22;
                    const size_t OUT_YZ   = OUT_XZ + (size_t)N * 22;
                    const float invxy = 1.f / (102.4f + 1e-6f);
                    const float invz  = 1.f / (8.0f + 1e-6f);

                    #pragma unroll
                    for (int mm = 0; mm < 2; ++mm) {
                        const int m = cpart + mm * 8;
                        if (m < 11) {
                            float lx, ly, lz;
                            if (m == 0)      { lx = 0.f;  ly = 0.f;  lz = 0.f; }
                            else if (m == 1) { lx = 0.f;  ly = sy;   lz = 0.f; }
                            else if (m == 2) { lx = 0.f;  ly = -sy;  lz = 0.f; }
                            else if (m == 3) { lx = sx;   ly = 0.f;  lz = 0.f; }
                            else if (m == 4) { lx = -sx;  ly = 0.f;  lz = 0.f; }
                            else {
                                const int j = (m - 5) * 3;
                                const float t0 = s[j]   + lfbs[j];
                                const float t1 = s[j+1] + lfbs[j+1];
                                const float t2 = s[j+2] + lfbs[j+2];
                                const float g0 = 1.f / (1.f + __expf(-t0));
                                const float g1 = 1.f / (1.f + __expf(-t1));
                                const float g2 = 1.f / (1.f + __expf(-t2));
                                lx = (g0 - 0.5f) * sx;
                                ly = (g1 - 0.5f) * sy;
                                lz = (g2 - 0.5f) * sz;
                            }
                            const float cxv = r00*lx + r01*ly + r02*lz + mx;
                            const float cyv = r10*lx + r11*ly + r12*lz + my;
                            const float czv = r20*lx + r21*ly + r22*lz + mz;
                            const size_t cb = OUT_CORN + ((size_t)row * 11 + m) * 3;
                            out[cb]   = cxv;
                            out[cb+1] = cyv;
                            out[cb+2] = czv;
                            const float nx = fminf(fmaxf((cxv + 51.2f) * invxy, 0.f), 1.f);
                            const float ny = fminf(fmaxf((cyv + 51.2f) * invxy, 0.f), 1.f);
                            const float nz = fminf(fmaxf((czv + 5.0f)  * invz,  0.f), 1.f);
                            const size_t rb2 = (size_t)row * 11 + m;
                            out[OUT_XY + rb2*2]     = nx;
                            out[OUT_XY + rb2*2 + 1] = ny;
                            out[OUT_XZ + rb2*2]     = nx;
                            out[OUT_XZ + rb2*2 + 1] = nz;
                            out[OUT_YZ + rb2*2]     = ny;
                            out[OUT_YZ + rb2*2 + 1] = nz;
                        }
                    }
                }
            }
            __syncthreads();
        }
    }
}

extern "C" void kernel_launch(void* const* d_in, const int* in_sizes, int n_in,
                              void* d_out, int out_size) {
    const float* mu    = (const float*)d_in[0];
    const float* sc    = (const float*)d_in[1];
    const float* rot   = (const float*)d_in[2];
    const float* Q     = (const float*)d_in[3];
    const float* w1    = (const float*)d_in[4];
    const float* b1    = (const float*)d_in[5];
    const float* gamma = (const float*)d_in[6];
    const float* beta  = (const float*)d_in[7];
    const float* w2    = (const float*)d_in[8];
    const float* b2    = (const float*)d_in[9];
    const float* lfw   = (const float*)d_in[10];
    const float* lfb   = (const float*)d_in[11];
    float* out = (float*)d_out;
    const int N = in_sizes[0] / 3;
    const int ntiles = (N + TILE - 1) / TILE;

    w2_convert_kernel<<<256, 256>>>(w2, lfw);

    const int smem = SMEM_FLOATS * sizeof(float);
    cudaFuncSetAttribute(gauss_persist_kernel,
                         cudaFuncAttributeMaxDynamicSharedMemorySize, smem);
    const int blocks = (ntiles < 148) ? ntiles : 148;
    gauss_persist_kernel<<<blocks, 512, smem>>>(
        mu, sc, rot, Q, w1, b1, gamma, beta, b2, lfb, out, N, ntiles);
}

// round 9
// speedup vs baseline: 3.2589x; 3.2589x over previous
#include <cuda_runtime.h>
#include <cuda_fp16.h>
#include <mma.h>
#include <cstdint>

using namespace nvcuda;
typedef unsigned int u32;

#define MT 64
#define LDH 264            // hs fp16 stride (528B rows)
#define LDFS 260           // fs fp32 stride
#define LDLW 36            // lfwt fp32 stride (cols padded 18->32, +4 pad)
#define LDLO 32            // lfout fp32 stride
#define NCHUNK 16

// ---------------- smem layout (floats) ----------------
// hs: 64 x 264 fp16 = 8448            [0, 8448)
// B : 4 bufs x (16 x 264 fp16 = 2112) [8448, 16896)
// fs: 64 x 260 fp32 = 16640 overlays [0,16640) post-GEMM
// geo: 640                            [16896, 17536)
// lfwt: 256 x 36 fp32 = 9216          [17536, 26752)
// lfout: 64 x 32 fp32 = 2048          [26752, 28800)
// lfbs: 32                            [28800, 28832)
#define HS_F    0
#define B_F     8448
#define GEO_F   16896
#define LFWT_F  17536
#define LFO_F   26752
#define LFB_F   28800
#define SMEM_FLOATS 28832            // 115,328 B -> 2 CTAs/SM

__device__ __half g_w2h[256 * 256];    // [K][N] fp16
__device__ float  g_lfwt[256 * LDLW];  // [K=256][32] padded lfw

__device__ __forceinline__ u32 smem_u32(const void* p) {
    return (u32)__cvta_generic_to_shared(p);
}
__device__ __forceinline__ void cp_async16(u32 s, const void* g) {
    asm volatile("cp.async.cg.shared.global [%0], [%1], 16;" :: "r"(s), "l"(g));
}
__device__ __forceinline__ void cp_commit() { asm volatile("cp.async.commit_group;"); }
template<int NN> __device__ __forceinline__ void cp_wait() {
    asm volatile("cp.async.wait_group %0;" :: "n"(NN) : "memory");
}

__global__ void w2_convert_kernel(const float* __restrict__ w2,
                                  const float* __restrict__ lfw) {
    const int k = blockIdx.x, n = threadIdx.x;
    g_w2h[k * 256 + n] = __float2half(w2[k * 256 + n]);
    if (n < LDLW)
        g_lfwt[k * LDLW + n] = (n < 18) ? lfw[k * 18 + n] : 0.f;
}

// stage a 16-k-row chunk of w2 fp16 into buffer buf (0..3)
__device__ __forceinline__ void load_chunk(u32 smb, int buf, int kt, int tid) {
    const u32 base = smb + B_F * 4 + buf * 8448;
    #pragma unroll
    for (int q = 0; q < 2; ++q) {
        const int idx = tid + 256 * q;          // 0..511
        const int r   = idx >> 5;               // k-row 0..15
        const int j   = idx & 31;               // 8-fp16 chunk
        cp_async16(base + r * 528 + j * 16, g_w2h + (kt + r) * 256 + j * 8);
    }
}

// =================== Fused kernel ===================
__global__ void __launch_bounds__(256, 2)
gauss_fused_kernel(const float* __restrict__ mu, const float* __restrict__ sc,
                   const float* __restrict__ rot, const float* __restrict__ Q,
                   const float* __restrict__ w1, const float* __restrict__ b1,
                   const float* __restrict__ gamma, const float* __restrict__ beta,
                   const float* __restrict__ b2, const float* __restrict__ lfb,
                   float* __restrict__ out, int N)
{
    extern __shared__ float sm[];
    const u32 smb = smem_u32(sm);
    __half* hs  = (__half*)(sm + HS_F);
    float* fs   = sm + HS_F;            // overlays hs+B post-GEMM
    float* mus  = sm + GEO_F;           // 192
    float* scs  = sm + GEO_F + 192;     // 192
    float* rots = sm + GEO_F + 384;     // 256
    float* lfwt = sm + LFWT_F;
    float* lfo  = sm + LFO_F;
    float* lfbs = sm + LFB_F;

    const int tid  = threadIdx.x;
    const int lane = tid & 31;
    const int wid  = tid >> 5;
    const int rowBase = blockIdx.x * MT;
    const bool fullTile = (rowBase + MT <= N);

    // ---- group G: lfwt + geo ----
    {
        const u32 lfdst = smb + LFWT_F * 4;
        #pragma unroll
        for (int q = 0; q < 9; ++q) {
            const int c = tid + 256 * q;      // 0..2303 chunks of 16B
            cp_async16(lfdst + c * 16, g_lfwt + c * 4);
        }
        if (fullTile) {
            if (tid < 48)
                cp_async16(smb + (GEO_F + tid * 4) * 4, mu + (size_t)rowBase * 3 + tid * 4);
            else if (tid >= 64 && tid < 112)
                cp_async16(smb + (GEO_F + 192 + (tid - 64) * 4) * 4, sc + (size_t)rowBase * 3 + (tid - 64) * 4);
            else if (tid >= 128 && tid < 192)
                cp_async16(smb + (GEO_F + 384 + (tid - 128) * 4) * 4, rot + (size_t)rowBase * 4 + (tid - 128) * 4);
        } else {
            #pragma unroll 1
            for (int idx = tid; idx < 640; idx += 256) {
                float v = 0.f;
                if (idx < 192)      { const int r = idx / 3;         if (rowBase + r < N) v = mu[(size_t)(rowBase + r) * 3 + idx % 3]; }
                else if (idx < 384) { const int r = (idx - 192) / 3; if (rowBase + r < N) v = sc[(size_t)(rowBase + r) * 3 + (idx - 192) % 3]; }
                else                { const int r = (idx - 384) / 4; if (rowBase + r < N) v = rot[(size_t)(rowBase + r) * 4 + (idx - 384) % 4]; }
                sm[GEO_F + idx] = v;
            }
        }
    }
    cp_commit();                                     // [G]
    load_chunk(smb, 0, 0, tid);  cp_commit();        // [G][B0]
    load_chunk(smb, 1, 16, tid); cp_commit();        // [G][B0][B1]
    load_chunk(smb, 2, 32, tid); cp_commit();        // [G][B0][B1][B2]

    if (tid < 18) lfbs[tid] = lfb[tid];
    const float b2v = __ldg(b2 + tid);

    cp_wait<3>();          // G done; B0..B2 in flight
    __syncthreads();

    // ---- phase 1: h = relu(LN(geo@w1+b1)) -> hs fp16 ; 4-row batches ----
    #pragma unroll 1
    for (int bb = 0; bb < 2; ++bb) {
        const int rl0 = wid * 8 + bb * 4;
        float g[4][10];
        #pragma unroll
        for (int r = 0; r < 4; ++r) {
            const int rl = rl0 + r;
            g[r][0]=mus[rl*3]; g[r][1]=mus[rl*3+1]; g[r][2]=mus[rl*3+2];
            g[r][3]=scs[rl*3]; g[r][4]=scs[rl*3+1]; g[r][5]=scs[rl*3+2];
            g[r][6]=rots[rl*4]; g[r][7]=rots[rl*4+1]; g[r][8]=rots[rl*4+2]; g[r][9]=rots[rl*4+3];
        }
        float hv[4][8];
        #pragma unroll
        for (int jj = 0; jj < 8; ++jj) {
            const int d = lane + 32 * jj;
            float w[10];
            #pragma unroll
            for (int i = 0; i < 10; ++i) w[i] = __ldg(w1 + i * 256 + d);
            const float bv = __ldg(b1 + d);
            #pragma unroll
            for (int r = 0; r < 4; ++r) {
                float a = bv;
                #pragma unroll
                for (int i = 0; i < 10; ++i) a = fmaf(g[r][i], w[i], a);
                hv[r][jj] = a;
            }
        }
        float s[4] = {0.f, 0.f, 0.f, 0.f};
        #pragma unroll
        for (int r = 0; r < 4; ++r)
            #pragma unroll
            for (int jj = 0; jj < 8; ++jj) s[r] += hv[r][jj];
        #pragma unroll
        for (int o = 16; o; o >>= 1) {
            #pragma unroll
            for (int r = 0; r < 4; ++r) s[r] += __shfl_xor_sync(0xffffffffu, s[r], o);
        }
        float v[4] = {0.f, 0.f, 0.f, 0.f};
        float mean[4];
        #pragma unroll
        for (int r = 0; r < 4; ++r) {
            mean[r] = s[r] * (1.f/256.f);
            #pragma unroll
            for (int jj = 0; jj < 8; ++jj) { float t = hv[r][jj] - mean[r]; v[r] = fmaf(t, t, v[r]); }
        }
        #pragma unroll
        for (int o = 16; o; o >>= 1) {
            #pragma unroll
            for (int r = 0; r < 4; ++r) v[r] += __shfl_xor_sync(0xffffffffu, v[r], o);
        }
        #pragma unroll
        for (int r = 0; r < 4; ++r) {
            const float inv = rsqrtf(v[r] * (1.f/256.f) + 1e-5f);
            const bool valid = (rowBase + rl0 + r < N);
            #pragma unroll
            for (int jj = 0; jj < 8; ++jj) {
                const int d = lane + 32 * jj;
                float t = (hv[r][jj] - mean[r]) * inv * __ldg(gamma + d) + __ldg(beta + d);
                t = fmaxf(t, 0.f);
                if (!valid) t = 0.f;
                hs[(rl0 + r) * LDH + d] = __float2half(t);
            }
        }
    }
    __syncthreads();

    // ---- phase 2: GEMM 64x256x256 (single fp16 B), warp tile 64x32 ----
    const int c0 = wid * 32;

    wmma::fragment<wmma::accumulator, 16,16,16, float> acc[4][2];
    #pragma unroll
    for (int mi = 0; mi < 4; ++mi)
        #pragma unroll
        for (int ni = 0; ni < 2; ++ni) wmma::fill_fragment(acc[mi][ni], 0.f);

    #pragma unroll 1
    for (int t = 0; t < NCHUNK; ++t) {
        if (t <= NCHUNK - 3)      { cp_wait<2>(); }
        else if (t == NCHUNK - 2) { cp_wait<1>(); }
        else                      { cp_wait<0>(); }
        __syncthreads();
        if (t + 3 < NCHUNK) { load_chunk(smb, (t + 3) & 3, (t + 3) * 16, tid); cp_commit(); }

        const __half* bh0 = (const __half*)(sm + B_F) + (t & 3) * 4224;
        const int kk = t * 16;

        wmma::fragment<wmma::matrix_a, 16,16,16, __half, wmma::row_major> a[4];
        #pragma unroll
        for (int mi = 0; mi < 4; ++mi)
            wmma::load_matrix_sync(a[mi], hs + (mi*16) * LDH + kk, LDH);

        #pragma unroll
        for (int ni = 0; ni < 2; ++ni) {
            wmma::fragment<wmma::matrix_b, 16,16,16, __half, wmma::row_major> b;
            wmma::load_matrix_sync(b, bh0 + c0 + ni*16, LDH);
            #pragma unroll
            for (int mi = 0; mi < 4; ++mi)
                wmma::mma_sync(acc[mi][ni], a[mi], b, acc[mi][ni]);
        }
    }
    __syncthreads();   // hs + B dead; fs takes over

    // ---- phase 3: acc -> fs ; features = fs + b2 + Q -> out + fs ----
    #pragma unroll
    for (int mi = 0; mi < 4; ++mi)
        #pragma unroll
        for (int ni = 0; ni < 2; ++ni)
            wmma::store_matrix_sync(fs + (mi*16) * LDFS + c0 + ni*16,
                                    acc[mi][ni], LDFS, wmma::mem_row_major);
    __syncthreads();

    #pragma unroll 1
    for (int rb = 0; rb < MT; rb += 8) {
        float qv[8];
        #pragma unroll
        for (int k = 0; k < 8; ++k) {
            const int row = rowBase + rb + k;
            qv[k] = (row < N) ? Q[(size_t)row * 256 + tid] : 0.f;
        }
        #pragma unroll
        for (int k = 0; k < 8; ++k) {
            const int row = rowBase + rb + k;
            const float v = fs[(rb + k) * LDFS + tid] + b2v + qv[k];
            if (row < N) out[(size_t)row * 256 + tid] = v;
            fs[(rb + k) * LDFS + tid] = v;
        }
    }
    __syncthreads();

    // ---- phase 3.5: lf logits = features @ lfw via tf32 wmma (64x32x256) ----
    {
        const int wm = wid & 3;       // 16-row frag
        const int nf = wid >> 2;      // 16-col frag (0/1)
        wmma::fragment<wmma::accumulator, 16,16,8, float> lacc;
        wmma::fill_fragment(lacc, 0.f);
        #pragma unroll 1
        for (int k = 0; k < 256; k += 8) {
            wmma::fragment<wmma::matrix_a, 16,16,8, wmma::precision::tf32, wmma::row_major> la;
            wmma::fragment<wmma::matrix_b, 16,16,8, wmma::precision::tf32, wmma::row_major> lb;
            wmma::load_matrix_sync(la, fs + (wm*16) * LDFS + k, LDFS);
            wmma::load_matrix_sync(lb, lfwt + k * LDLW + nf*16, LDLW);
            #pragma unroll
            for (int e = 0; e < la.num_elements; ++e) la.x[e] = wmma::__float_to_tf32(la.x[e]);
            #pragma unroll
            for (int e = 0; e < lb.num_elements; ++e) lb.x[e] = wmma::__float_to_tf32(lb.x[e]);
            wmma::mma_sync(lacc, la, lb, lacc);
        }
        wmma::store_matrix_sync(lfo + (wm*16) * LDLO + nf*16, lacc, LDLO, wmma::mem_row_major);
    }
    __syncthreads();

    // ---- phase 4: sigmoid + corners + refs ----
    {
        const int rl    = wid * 8 + (lane >> 2);
        const int cpart = lane & 3;
        const int row   = rowBase + rl;

        if (row < N) {
            const float mx = mus[rl*3], my = mus[rl*3+1], mz = mus[rl*3+2];
            const float sx = scs[rl*3]*0.5f, sy = scs[rl*3+1]*0.5f, sz = scs[rl*3+2]*0.5f;
            float qw = rots[rl*4], qx = rots[rl*4+1], qy = rots[rl*4+2], qz = rots[rl*4+3];
            const float nrm = fmaxf(sqrtf(qw*qw + qx*qx + qy*qy + qz*qz), 1e-8f);
            const float inr = 1.f / nrm;
            qw *= inr; qx *= inr; qy *= inr; qz *= inr;
            const float r00 = 1.f - 2.f*(qy*qy + qz*qz), r01 = 2.f*(qx*qy - qz*qw), r02 = 2.f*(qx*qz + qy*qw);
            const float r10 = 2.f*(qx*qy + qz*qw), r11 = 1.f - 2.f*(qx*qx + qz*qz), r12 = 2.f*(qy*qz - qx*qw);
            const float r20 = 2.f*(qx*qz - qy*qw), r21 = 2.f*(qy*qz + qx*qw), r22 = 1.f - 2.f*(qx*qx + qy*qy);

            const size_t OUT_CORN = (size_t)N * 256;
            const size_t OUT_XY   = OUT_CORN + (size_t)N * 33;
            const size_t OUT_XZ   = OUT_XY + (size_t)N * 22;
            const size_t OUT_YZ   = OUT_XZ + (size_t)N * 22;
            const float invxy = 1.f / (102.4f + 1e-6f);
            const float invz  = 1.f / (8.0f + 1e-6f);

            #pragma unroll
            for (int mm = 0; mm < 3; ++mm) {
                const int m = cpart + mm * 4;
                if (m < 11) {
                    float lx, ly, lz;
                    if (m == 0)      { lx = 0.f;  ly = 0.f;  lz = 0.f; }
                    else if (m == 1) { lx = 0.f;  ly = sy;   lz = 0.f; }
                    else if (m == 2) { lx = 0.f;  ly = -sy;  lz = 0.f; }
                    else if (m == 3) { lx = sx;   ly = 0.f;  lz = 0.f; }
                    else if (m == 4) { lx = -sx;  ly = 0.f;  lz = 0.f; }
                    else {
                        const int j = (m - 5) * 3;
                        const float t0 = lfo[rl * LDLO + j]     + lfbs[j];
                        const float t1 = lfo[rl * LDLO + j + 1] + lfbs[j + 1];
                        const float t2 = lfo[rl * LDLO + j + 2] + lfbs[j + 2];
                        const float g0 = 1.f / (1.f + __expf(-t0));
                        const float g1 = 1.f / (1.f + __expf(-t1));
                        const float g2 = 1.f / (1.f + __expf(-t2));
                        lx = (g0 - 0.5f) * sx;
                        ly = (g1 - 0.5f) * sy;
                        lz = (g2 - 0.5f) * sz;
                    }
                    const float cxv = r00*lx + r01*ly + r02*lz + mx;
                    const float cyv = r10*lx + r11*ly + r12*lz + my;
                    const float czv = r20*lx + r21*ly + r22*lz + mz;
                    const size_t cb = OUT_CORN + ((size_t)row * 11 + m) * 3;
                    out[cb]   = cxv;
                    out[cb+1] = cyv;
                    out[cb+2] = czv;
                    const float nx = fminf(fmaxf((cxv + 51.2f) * invxy, 0.f), 1.f);
                    const float ny = fminf(fmaxf((cyv + 51.2f) * invxy, 0.f), 1.f);
                    const float nz = fminf(fmaxf((czv + 5.0f)  * invz,  0.f), 1.f);
                    const size_t rb2 = (size_t)row * 11 + m;
                    out[OUT_XY + rb2*2]     = nx;
                    out[OUT_XY + rb2*2 + 1] = ny;
                    out[OUT_XZ + rb2*2]     = nx;
                    out[OUT_XZ + rb2*2 + 1] = nz;
                    out[OUT_YZ + rb2*2]     = ny;
                    out[OUT_YZ + rb2*2 + 1] = nz;
                }
            }
        }
    }
}

extern "C" void kernel_launch(void* const* d_in, const int* in_sizes, int n_in,
                              void* d_out, int out_size) {
    const float* mu    = (const float*)d_in[0];
    const float* sc    = (const float*)d_in[1];
    const float* rot   = (const float*)d_in[2];
    const float* Q     = (const float*)d_in[3];
    const float* w1    = (const float*)d_in[4];
    const float* b1    = (const float*)d_in[5];
    const float* gamma = (const float*)d_in[6];
    const float* beta  = (const float*)d_in[7];
    const float* w2    = (const float*)d_in[8];
    const float* b2    = (const float*)d_in[9];
    const float* lfw   = (const float*)d_in[10];
    const float* lfb   = (const float*)d_in[11];
    float* out = (float*)d_out;
    const int N = in_sizes[0] / 3;

    w2_convert_kernel<<<256, 256>>>(w2, lfw);

    const int smem = SMEM_FLOATS * sizeof(float);
    cudaFuncSetAttribute(gauss_fused_kernel,
                         cudaFuncAttributeMaxDynamicSharedMemorySize, smem);
    const int blocks = (N + MT - 1) / MT;
    gauss_fused_kernel<<<blocks, 256, smem>>>(
        mu, sc, rot, Q, w1, b1, gamma, beta, b2, lfb, out, N);
}